// round 1
// baseline (speedup 1.0000x reference)
#include <cuda_runtime.h>
#include <cuda_bf16.h>

typedef unsigned long long u64;

// ---- packed f32x2 helpers (sm_100+ PTX; not emitted by ptxas from C++) ----
__device__ __forceinline__ u64 pack2(float lo, float hi) {
    u64 r; asm("mov.b64 %0, {%1, %2};" : "=l"(r) : "f"(lo), "f"(hi)); return r;
}
__device__ __forceinline__ void unpack2(u64 v, float& lo, float& hi) {
    asm("mov.b64 {%0, %1}, %2;" : "=f"(lo), "=f"(hi) : "l"(v));
}
__device__ __forceinline__ u64 fma2(u64 a, u64 b, u64 c) {
    u64 d; asm("fma.rn.f32x2 %0, %1, %2, %3;" : "=l"(d) : "l"(a), "l"(b), "l"(c)); return d;
}

__device__ __forceinline__ float elu1(float x) {
    return x > 0.f ? x : (__expf(x) - 1.f);
}

// Problem constants (fixed shapes): 4096x4096 fp32, BLOCK=256, TILE=4,
// nb=256 weight-blocks, 64x64=4096 tiles/block, RNG_HID=96, RNG_POS_EMB=8.
__global__ __launch_bounds__(256, 2) void adapter_kernel(
    const float* __restrict__ A,        // [4096,4096]
    const float* __restrict__ w1,       // [256,16,96]
    const float* __restrict__ b1,       // [256,96]
    const float* __restrict__ emb_h,    // [256,64,8]
    const float* __restrict__ emb_w,    // [256,64,8]
    const float* __restrict__ w2,       // [256,96,16]
    const float* __restrict__ b2,       // [256,16]
    const float* __restrict__ scales,   // [256,16]
    float* __restrict__ out)            // [4096,4096]
{
    __shared__ __align__(16) float s_w1[16 * 96];
    __shared__ __align__(16) float s_w2[96 * 16];
    __shared__ __align__(16) float s_b1[96];
    __shared__ __align__(16) float s_eh[64 * 8];
    __shared__ __align__(16) float s_ew[64 * 8];
    __shared__ __align__(16) float s_b2[16];
    __shared__ __align__(16) float s_sc[16];

    const int b     = blockIdx.x >> 4;   // weight-block 0..255
    const int chunk = blockIdx.x & 15;   // 256-tile chunk within block
    const int tid   = threadIdx.x;

    // ---- cooperative smem staging ----
    {
        const float* p1 = w1 + b * 1536;
        const float* p2 = w2 + b * 1536;
        #pragma unroll
        for (int i = 0; i < 6; ++i) {
            s_w1[tid + 256 * i] = p1[tid + 256 * i];
            s_w2[tid + 256 * i] = p2[tid + 256 * i];
        }
        #pragma unroll
        for (int i = 0; i < 2; ++i) {
            s_eh[tid + 256 * i] = emb_h[b * 512 + tid + 256 * i];
            s_ew[tid + 256 * i] = emb_w[b * 512 + tid + 256 * i];
        }
        if (tid < 96)                    s_b1[tid]      = b1[b * 96 + tid];
        if (tid >= 128 && tid < 144)     s_b2[tid - 128] = b2[b * 16 + tid - 128];
        if (tid >= 160 && tid < 176)     s_sc[tid - 160] = scales[b * 16 + tid - 160];
    }
    __syncthreads();

    // ---- tile coordinates ----
    const int t    = chunk * 256 + tid;   // tile id 0..4095
    const int th   = t >> 6;              // tile row in block
    const int tw   = t & 63;              // tile col in block
    const int row0 = ((b >> 4) << 8) + (th << 2);
    const int col0 = ((b & 15) << 8) + (tw << 2);
    const float* ap = A + (size_t)row0 * 4096 + col0;

    // ---- load 4x4 tile (coalesced float4 per row) ----
    float flat[16];
    #pragma unroll
    for (int r = 0; r < 4; ++r) {
        float4 v = *reinterpret_cast<const float4*>(ap + (size_t)r * 4096);
        flat[4 * r + 0] = v.x; flat[4 * r + 1] = v.y;
        flat[4 * r + 2] = v.z; flat[4 * r + 3] = v.w;
    }

    // ---- output accumulators: b2 + flat * scales (residual) ----
    u64 outa[8];
    #pragma unroll
    for (int jj = 0; jj < 8; ++jj) {
        float o0 = s_b2[2 * jj]     + flat[2 * jj]     * s_sc[2 * jj];
        float o1 = s_b2[2 * jj + 1] + flat[2 * jj + 1] * s_sc[2 * jj + 1];
        outa[jj] = pack2(o0, o1);
    }

    // ---- hidden in two 48-channel chunks (24 packed accumulators each) ----
    #pragma unroll
    for (int ch = 0; ch < 2; ++ch) {
        const int h0 = ch * 48;
        u64 acc[24];
        // init: bias + positional embeddings (channels 0..7: emb_h[th], 8..15: emb_w[tw])
        #pragma unroll
        for (int p = 0; p < 24; ++p) {
            float a0 = s_b1[h0 + 2 * p];
            float a1 = s_b1[h0 + 2 * p + 1];
            if (ch == 0) {
                if (2 * p < 8)       { a0 += s_eh[th * 8 + 2 * p];     a1 += s_eh[th * 8 + 2 * p + 1]; }
                else if (2 * p < 16) { a0 += s_ew[tw * 8 + 2 * p - 8]; a1 += s_ew[tw * 8 + 2 * p - 7]; }
            }
            acc[p] = pack2(a0, a1);
        }
        // layer 1: hid += flat[k] * w1[k][h]  (16 x 24 packed FMAs)
        #pragma unroll
        for (int k = 0; k < 16; ++k) {
            u64 aa = pack2(flat[k], flat[k]);
            const u64* wrow = reinterpret_cast<const u64*>(s_w1 + k * 96 + h0);
            #pragma unroll
            for (int p = 0; p < 24; ++p) acc[p] = fma2(aa, wrow[p], acc[p]);
        }
        // ELU + layer 2: out[j] += elu(hid[h]) * w2[h][j]
        #pragma unroll
        for (int p = 0; p < 24; ++p) {
            float g0, g1; unpack2(acc[p], g0, g1);
            g0 = elu1(g0); g1 = elu1(g1);
            const int h = h0 + 2 * p;
            u64 gg0 = pack2(g0, g0);
            u64 gg1 = pack2(g1, g1);
            const u64* r0 = reinterpret_cast<const u64*>(s_w2 + h * 16);
            const u64* r1 = reinterpret_cast<const u64*>(s_w2 + (h + 1) * 16);
            #pragma unroll
            for (int jj = 0; jj < 8; ++jj) {
                outa[jj] = fma2(gg0, r0[jj], outa[jj]);
                outa[jj] = fma2(gg1, r1[jj], outa[jj]);
            }
        }
    }

    // ---- store 4x4 tile (coalesced float4 per row) ----
    float o[16];
    #pragma unroll
    for (int jj = 0; jj < 8; ++jj) unpack2(outa[jj], o[2 * jj], o[2 * jj + 1]);
    float* op = out + (size_t)row0 * 4096 + col0;
    #pragma unroll
    for (int r = 0; r < 4; ++r) {
        float4 v = make_float4(o[4 * r], o[4 * r + 1], o[4 * r + 2], o[4 * r + 3]);
        *reinterpret_cast<float4*>(op + (size_t)r * 4096) = v;
    }
}

extern "C" void kernel_launch(void* const* d_in, const int* in_sizes, int n_in,
                              void* d_out, int out_size) {
    const float* A      = (const float*)d_in[0];
    const float* w1     = (const float*)d_in[1];
    const float* b1     = (const float*)d_in[2];
    const float* emb_h  = (const float*)d_in[3];
    const float* emb_w  = (const float*)d_in[4];
    const float* w2     = (const float*)d_in[5];
    const float* b2     = (const float*)d_in[6];
    const float* scales = (const float*)d_in[7];
    float* out = (float*)d_out;
    (void)in_sizes; (void)n_in; (void)out_size;

    adapter_kernel<<<4096, 256>>>(A, w1, b1, emb_h, emb_w, w2, b2, scales, out);
}

// round 2
// speedup vs baseline: 1.1252x; 1.1252x over previous
#include <cuda_runtime.h>
#include <cuda_bf16.h>

typedef unsigned long long u64;

// ---- packed f32x2 helpers (sm_100+; ptxas never auto-fuses these) ----
__device__ __forceinline__ u64 pack2(float lo, float hi) {
    u64 r; asm("mov.b64 %0, {%1, %2};" : "=l"(r) : "f"(lo), "f"(hi)); return r;
}
__device__ __forceinline__ void unpack2(u64 v, float& lo, float& hi) {
    asm("mov.b64 {%0, %1}, %2;" : "=f"(lo), "=f"(hi) : "l"(v));
}
__device__ __forceinline__ u64 fma2(u64 a, u64 b, u64 c) {
    u64 d; asm("fma.rn.f32x2 %0, %1, %2, %3;" : "=l"(d) : "l"(a), "l"(b), "l"(c)); return d;
}

__device__ __forceinline__ float elu1(float x) {
    return x > 0.f ? x : (__expf(x) - 1.f);
}

// Fixed shapes: 4096x4096 fp32, BLOCK=256, TILE=4, nb=256 weight-blocks,
// 64x64=4096 tiles/block, RNG_HID=96, RNG_POS_EMB=8.
// Grid: 256 blocks x 16 chunks = 4096 CTAs of 128 threads.
// Each thread processes 2 tiles (tid and tid+128 within its 256-tile chunk),
// amortizing every shared-memory weight read over 2 tiles' FMAs.
__global__ __launch_bounds__(128, 3) void adapter_kernel(
    const float* __restrict__ A,        // [4096,4096]
    const float* __restrict__ w1,       // [256,16,96]
    const float* __restrict__ b1,       // [256,96]
    const float* __restrict__ emb_h,    // [256,64,8]
    const float* __restrict__ emb_w,    // [256,64,8]
    const float* __restrict__ w2,       // [256,96,16]
    const float* __restrict__ b2,       // [256,16]
    const float* __restrict__ scales,   // [256,16]
    float* __restrict__ out)            // [4096,4096]
{
    __shared__ __align__(16) float s_w1[16 * 96];
    __shared__ __align__(16) float s_w2[96 * 16];
    __shared__ __align__(16) float s_b1[96];
    __shared__ __align__(16) float s_eh[64 * 8];
    __shared__ __align__(16) float s_ew[64 * 8];
    __shared__ __align__(16) float s_b2[16];
    __shared__ __align__(16) float s_sc[16];

    const int b     = blockIdx.x >> 4;   // weight-block 0..255
    const int chunk = blockIdx.x & 15;   // 256-tile chunk within block
    const int tid   = threadIdx.x;       // 0..127

    // ---- cooperative smem staging (128 threads) ----
    {
        const float* p1 = w1 + b * 1536;
        const float* p2 = w2 + b * 1536;
        #pragma unroll
        for (int i = 0; i < 12; ++i) {
            s_w1[tid + 128 * i] = p1[tid + 128 * i];
            s_w2[tid + 128 * i] = p2[tid + 128 * i];
        }
        #pragma unroll
        for (int i = 0; i < 4; ++i) {
            s_eh[tid + 128 * i] = emb_h[b * 512 + tid + 128 * i];
            s_ew[tid + 128 * i] = emb_w[b * 512 + tid + 128 * i];
        }
        if (tid < 96) s_b1[tid] = b1[b * 96 + tid];
        if (tid < 16) {
            s_b2[tid] = b2[b * 16 + tid];
            s_sc[tid] = scales[b * 16 + tid];
        }
    }
    __syncthreads();

    // ---- tile coordinates for both tiles ----
    const int t0  = chunk * 256 + tid;       // tile 0
    const int t1  = t0 + 128;                // tile 1
    const int th0 = t0 >> 6, tw0 = t0 & 63;
    const int th1 = t1 >> 6, tw1 = t1 & 63;
    const int brow = (b >> 4) << 8;          // block row origin
    const int bcol = (b & 15) << 8;          // block col origin
    const float* ap0 = A + (size_t)(brow + (th0 << 2)) * 4096 + bcol + (tw0 << 2);
    const float* ap1 = A + (size_t)(brow + (th1 << 2)) * 4096 + bcol + (tw1 << 2);

    // ---- load both 4x4 tiles up front (8 LDG.128, front-batched for MLP) ----
    float fl0[16], fl1[16];
    #pragma unroll
    for (int r = 0; r < 4; ++r) {
        float4 v0 = *reinterpret_cast<const float4*>(ap0 + (size_t)r * 4096);
        float4 v1 = *reinterpret_cast<const float4*>(ap1 + (size_t)r * 4096);
        fl0[4*r+0] = v0.x; fl0[4*r+1] = v0.y; fl0[4*r+2] = v0.z; fl0[4*r+3] = v0.w;
        fl1[4*r+0] = v1.x; fl1[4*r+1] = v1.y; fl1[4*r+2] = v1.z; fl1[4*r+3] = v1.w;
    }

    // ---- output accumulators: b2 + flat * scales (residual) ----
    u64 oa0[8], oa1[8];
    #pragma unroll
    for (int jj = 0; jj < 8; ++jj) {
        const float2 bb = *reinterpret_cast<const float2*>(s_b2 + 2*jj);
        const float2 ss = *reinterpret_cast<const float2*>(s_sc + 2*jj);
        oa0[jj] = pack2(bb.x + fl0[2*jj] * ss.x, bb.y + fl0[2*jj+1] * ss.y);
        oa1[jj] = pack2(bb.x + fl1[2*jj] * ss.x, bb.y + fl1[2*jj+1] * ss.y);
    }

    // ---- hidden processed in 6 chunks of 16 channels ----
    #pragma unroll
    for (int c = 0; c < 6; ++c) {
        const int h0 = c * 16;
        u64 a0[8], a1[8];
        // init: bias (+ positional embeddings only in chunk 0: ch 0..7 eh, 8..15 ew)
        #pragma unroll
        for (int p = 0; p < 8; ++p) {
            const float2 bb = *reinterpret_cast<const float2*>(s_b1 + h0 + 2*p);
            float x0 = bb.x, x1 = bb.y, y0 = bb.x, y1 = bb.y;
            if (c == 0) {
                if (p < 4) {
                    x0 += s_eh[th0*8 + 2*p]; x1 += s_eh[th0*8 + 2*p + 1];
                    y0 += s_eh[th1*8 + 2*p]; y1 += s_eh[th1*8 + 2*p + 1];
                } else {
                    x0 += s_ew[tw0*8 + 2*p - 8]; x1 += s_ew[tw0*8 + 2*p - 7];
                    y0 += s_ew[tw1*8 + 2*p - 8]; y1 += s_ew[tw1*8 + 2*p - 7];
                }
            }
            a0[p] = pack2(x0, x1);
            a1[p] = pack2(y0, y1);
        }

        // layer 1: hid[h] += flat[k] * w1[k][h]   (per k: 4 LDS.128, 16 FMA2)
        #pragma unroll
        for (int k = 0; k < 16; ++k) {
            const float4* wr = reinterpret_cast<const float4*>(s_w1 + k * 96 + h0);
            const u64 c0 = pack2(fl0[k], fl0[k]);
            const u64 c1 = pack2(fl1[k], fl1[k]);
            #pragma unroll
            for (int q = 0; q < 4; ++q) {
                const float4 w = wr[q];
                const u64 wlo = pack2(w.x, w.y);
                const u64 whi = pack2(w.z, w.w);
                a0[2*q]   = fma2(c0, wlo, a0[2*q]);
                a0[2*q+1] = fma2(c0, whi, a0[2*q+1]);
                a1[2*q]   = fma2(c1, wlo, a1[2*q]);
                a1[2*q+1] = fma2(c1, whi, a1[2*q+1]);
            }
        }

        // ELU + layer 2: out[j] += elu(hid[h]) * w2[h][j]
        // per p: 8 LDS.128 (two w2 rows), 32 FMA2
        #pragma unroll
        for (int p = 0; p < 8; ++p) {
            float g00, g01, g10, g11;
            unpack2(a0[p], g00, g01);
            unpack2(a1[p], g10, g11);
            g00 = elu1(g00); g01 = elu1(g01);
            g10 = elu1(g10); g11 = elu1(g11);
            const int h = h0 + 2*p;
            const float4* r0 = reinterpret_cast<const float4*>(s_w2 + h * 16);
            const float4* r1 = reinterpret_cast<const float4*>(s_w2 + (h + 1) * 16);
            const u64 e00 = pack2(g00, g00);
            const u64 e01 = pack2(g01, g01);
            const u64 e10 = pack2(g10, g10);
            const u64 e11 = pack2(g11, g11);
            #pragma unroll
            for (int q = 0; q < 4; ++q) {
                const float4 wa = r0[q];
                const float4 wb = r1[q];
                const u64 wa_lo = pack2(wa.x, wa.y), wa_hi = pack2(wa.z, wa.w);
                const u64 wb_lo = pack2(wb.x, wb.y), wb_hi = pack2(wb.z, wb.w);
                oa0[2*q]   = fma2(e00, wa_lo, oa0[2*q]);
                oa0[2*q+1] = fma2(e00, wa_hi, oa0[2*q+1]);
                oa0[2*q]   = fma2(e01, wb_lo, oa0[2*q]);
                oa0[2*q+1] = fma2(e01, wb_hi, oa0[2*q+1]);
                oa1[2*q]   = fma2(e10, wa_lo, oa1[2*q]);
                oa1[2*q+1] = fma2(e10, wa_hi, oa1[2*q+1]);
                oa1[2*q]   = fma2(e11, wb_lo, oa1[2*q]);
                oa1[2*q+1] = fma2(e11, wb_hi, oa1[2*q+1]);
            }
        }
    }

    // ---- store both 4x4 tiles (coalesced float4 per row) ----
    float o0[16], o1[16];
    #pragma unroll
    for (int jj = 0; jj < 8; ++jj) {
        unpack2(oa0[jj], o0[2*jj], o0[2*jj+1]);
        unpack2(oa1[jj], o1[2*jj], o1[2*jj+1]);
    }
    float* op0 = out + (size_t)(brow + (th0 << 2)) * 4096 + bcol + (tw0 << 2);
    float* op1 = out + (size_t)(brow + (th1 << 2)) * 4096 + bcol + (tw1 << 2);
    #pragma unroll
    for (int r = 0; r < 4; ++r) {
        *reinterpret_cast<float4*>(op0 + (size_t)r * 4096) =
            make_float4(o0[4*r], o0[4*r+1], o0[4*r+2], o0[4*r+3]);
        *reinterpret_cast<float4*>(op1 + (size_t)r * 4096) =
            make_float4(o1[4*r], o1[4*r+1], o1[4*r+2], o1[4*r+3]);
    }
}

extern "C" void kernel_launch(void* const* d_in, const int* in_sizes, int n_in,
                              void* d_out, int out_size) {
    const float* A      = (const float*)d_in[0];
    const float* w1     = (const float*)d_in[1];
    const float* b1     = (const float*)d_in[2];
    const float* emb_h  = (const float*)d_in[3];
    const float* emb_w  = (const float*)d_in[4];
    const float* w2     = (const float*)d_in[5];
    const float* b2     = (const float*)d_in[6];
    const float* scales = (const float*)d_in[7];
    float* out = (float*)d_out;
    (void)in_sizes; (void)n_in; (void)out_size;

    adapter_kernel<<<4096, 128>>>(A, w1, b1, emb_h, emb_w, w2, b2, scales, out);
}

// round 3
// speedup vs baseline: 2.5869x; 2.2991x over previous
#include <cuda_runtime.h>
#include <cuda_bf16.h>

// ---------- helpers ----------
__device__ __forceinline__ unsigned pkbf(float lo, float hi) {
    // packed bf16x2: lo -> bits[0:16), hi -> bits[16:32)
    unsigned d; asm("cvt.rn.bf16x2.f32 %0, %1, %2;" : "=r"(d) : "f"(hi), "f"(lo)); return d;
}
__device__ __forceinline__ void mma16816(float& d0, float& d1, float& d2, float& d3,
                                         unsigned a0, unsigned a1, unsigned a2, unsigned a3,
                                         unsigned b0, unsigned b1) {
    asm("mma.sync.aligned.m16n8k16.row.col.f32.bf16.bf16.f32 "
        "{%0,%1,%2,%3},{%4,%5,%6,%7},{%8,%9},{%0,%1,%2,%3};"
        : "+f"(d0), "+f"(d1), "+f"(d2), "+f"(d3)
        : "r"(a0), "r"(a1), "r"(a2), "r"(a3), "r"(b0), "r"(b1));
}
__device__ __forceinline__ float elu1(float x) {
    return x > 0.f ? x : (__expf(x) - 1.f);
}

// Fixed shapes: A 4096x4096 fp32; BLOCK=256, TILE=4 -> nb=256 weight-blocks of
// 64x64=4096 tiles; RNG_HID=96, RNG_POS_EMB=8.
// Grid: 256 blocks x 16 chunks = 4096 CTAs x 128 threads (4 warps).
// Each CTA: 256 tiles = 16 M-blocks of 16 tiles; warp w handles M-blocks 4w..4w+3.
// Layer1: one m16n8k16 MMA per (M-block, n-block of 8 hidden ch): K=16.
// Layer2: 6 k-steps of m16n8k16 over hidden=96, N=16 outputs.

// smem strides chosen for conflict-free B/A-fragment access:
#define W1P_STRIDE 104   // = 96+8; 104 % 32 == 8 -> bank = 8*q + n, distinct
#define W2P_STRIDE 24    // 24 % 32 == 24 -> bank = 24*q + n, distinct
#define G_STRIDE   68    // = 48+20; 68 % 32 == 4 -> bank = 4*t + hp, distinct

__global__ __launch_bounds__(128, 4) void adapter_mma_kernel(
    const float* __restrict__ A,        // [4096,4096]
    const float* __restrict__ w1,       // [256,16,96]
    const float* __restrict__ b1,       // [256,96]
    const float* __restrict__ emb_h,    // [256,64,8]
    const float* __restrict__ emb_w,    // [256,64,8]
    const float* __restrict__ w2,       // [256,96,16]
    const float* __restrict__ b2,       // [256,16]
    const float* __restrict__ scales,   // [256,16]
    float* __restrict__ out)            // [4096,4096]
{
    __shared__ __align__(16) unsigned s_w1p[8 * W1P_STRIDE];    // bf16x2 k-pairs of w1
    __shared__ __align__(16) unsigned s_w2p[48 * W2P_STRIDE];   // bf16x2 k-pairs of w2
    __shared__ __align__(16) unsigned s_g[4][16 * G_STRIDE];    // per-warp elu(hid) bf16x2
    __shared__ __align__(16) float s_b1[96];
    __shared__ __align__(16) float s_eh[64 * 8];
    __shared__ __align__(16) float s_ew[64 * 8];
    __shared__ __align__(16) float s_b2[16];
    __shared__ __align__(16) float s_sc[16];

    const int b     = blockIdx.x >> 4;
    const int chunk = blockIdx.x & 15;
    const int tid   = threadIdx.x;
    const int warp  = tid >> 5;
    const int lane  = tid & 31;
    const int g     = lane >> 2;   // 0..7
    const int q     = lane & 3;    // 0..3

    // ---- stage weights (pack k-pairs into bf16x2) + biases/embeddings ----
    {
        const float* p1 = w1 + b * 1536;   // [16][96]
        const float* p2 = w2 + b * 1536;   // [96][16]
        #pragma unroll
        for (int i = tid; i < 768; i += 128) {         // w1p: kp = k/2 (0..7), n (0..95)
            int kp = i / 96, n = i - kp * 96;
            s_w1p[kp * W1P_STRIDE + n] = pkbf(p1[(2 * kp) * 96 + n], p1[(2 * kp + 1) * 96 + n]);
        }
        #pragma unroll
        for (int i = tid; i < 768; i += 128) {         // w2p: kp = h/2 (0..47), n (0..15)
            int kp = i / 16, n = i - kp * 16;
            s_w2p[kp * W2P_STRIDE + n] = pkbf(p2[(2 * kp) * 16 + n], p2[(2 * kp + 1) * 16 + n]);
        }
        #pragma unroll
        for (int i = 0; i < 4; ++i) {
            s_eh[tid + 128 * i] = emb_h[b * 512 + tid + 128 * i];
            s_ew[tid + 128 * i] = emb_w[b * 512 + tid + 128 * i];
        }
        if (tid < 96) s_b1[tid] = b1[b * 96 + tid];
        if (tid < 16) { s_b2[tid] = b2[b * 16 + tid]; s_sc[tid] = scales[b * 16 + tid]; }
    }
    __syncthreads();

    const int brow = (b >> 4) << 8;
    const int bcol = (b & 15) << 8;
    unsigned* gw = s_g[warp];

    #pragma unroll
    for (int it = 0; it < 4; ++it) {
        const int mb  = warp * 4 + it;                 // M-block 0..15
        const int t0  = chunk * 256 + mb * 16;         // first tile id
        const int th  = t0 >> 6;                       // tile row (same for whole M-block)
        const int twb = t0 & 63;                       // first tile col
        const int rowA = brow + th * 4;                // matrix row base of this tile row
        const int colA = bcol + (twb + g) * 4 + 2 * (q & 1);
        const int rsel = q >> 1;                       // sub-row within tile from k

        // ---- layer-1 A fragment: flat[t, k] direct from GMEM (coalesced float2) ----
        const float2 v0 = *reinterpret_cast<const float2*>(A + (size_t)(rowA + rsel)     * 4096 + colA);        // a0: t=g,   k=2q,2q+1
        const float2 v1 = *reinterpret_cast<const float2*>(A + (size_t)(rowA + rsel)     * 4096 + colA + 32);   // a1: t=g+8
        const float2 v2 = *reinterpret_cast<const float2*>(A + (size_t)(rowA + 2 + rsel) * 4096 + colA);        // a2: k+8
        const float2 v3 = *reinterpret_cast<const float2*>(A + (size_t)(rowA + 2 + rsel) * 4096 + colA + 32);   // a3
        const unsigned a0 = pkbf(v0.x, v0.y);
        const unsigned a1 = pkbf(v1.x, v1.y);
        const unsigned a2 = pkbf(v2.x, v2.y);
        const unsigned a3 = pkbf(v3.x, v3.y);

        // ---- layer 1: 12 n-blocks of 8 hidden channels; K=16 in one MMA ----
        #pragma unroll
        for (int nb = 0; nb < 12; ++nb) {
            const unsigned wb0 = s_w1p[q * W1P_STRIDE + 8 * nb + g];
            const unsigned wb1 = s_w1p[(q + 4) * W1P_STRIDE + 8 * nb + g];
            float d0 = 0.f, d1 = 0.f, d2 = 0.f, d3 = 0.f;
            mma16816(d0, d1, d2, d3, a0, a1, a2, a3, wb0, wb1);

            // bias + positional embeddings (h = 8*nb + 2q + {0,1})
            const float2 bb = *reinterpret_cast<const float2*>(s_b1 + 8 * nb + 2 * q);
            d0 += bb.x; d1 += bb.y; d2 += bb.x; d3 += bb.y;
            if (nb == 0) {   // h < 8: emb_h[th], same for all tiles of the M-block
                const float2 e = *reinterpret_cast<const float2*>(s_eh + th * 8 + 2 * q);
                d0 += e.x; d1 += e.y; d2 += e.x; d3 += e.y;
            }
            if (nb == 1) {   // 8 <= h < 16: emb_w[tw], tw = twb+g (rows t) / twb+g+8 (rows t+8)
                const float2 ea = *reinterpret_cast<const float2*>(s_ew + (twb + g) * 8 + 2 * q);
                const float2 eb = *reinterpret_cast<const float2*>(s_ew + (twb + g + 8) * 8 + 2 * q);
                d0 += ea.x; d1 += ea.y; d2 += eb.x; d3 += eb.y;
            }
            d0 = elu1(d0); d1 = elu1(d1); d2 = elu1(d2); d3 = elu1(d3);
            // store g as bf16x2 h-pairs: hpair index = 4*nb + q
            gw[g * G_STRIDE + 4 * nb + q]       = pkbf(d0, d1);
            gw[(g + 8) * G_STRIDE + 4 * nb + q] = pkbf(d2, d3);
        }
        __syncwarp();

        // ---- layer 2: out[16t,16] = g @ w2, K=96 (6 k-steps), N=16 (2 n-blocks) ----
        float o00 = 0.f, o01 = 0.f, o02 = 0.f, o03 = 0.f;
        float o10 = 0.f, o11 = 0.f, o12 = 0.f, o13 = 0.f;
        #pragma unroll
        for (int kb = 0; kb < 6; ++kb) {
            const unsigned ga0 = gw[g * G_STRIDE + 8 * kb + q];
            const unsigned ga1 = gw[(g + 8) * G_STRIDE + 8 * kb + q];
            const unsigned ga2 = gw[g * G_STRIDE + 8 * kb + 4 + q];
            const unsigned ga3 = gw[(g + 8) * G_STRIDE + 8 * kb + 4 + q];
            const unsigned wb00 = s_w2p[(8 * kb + q) * W2P_STRIDE + g];
            const unsigned wb01 = s_w2p[(8 * kb + q + 4) * W2P_STRIDE + g];
            mma16816(o00, o01, o02, o03, ga0, ga1, ga2, ga3, wb00, wb01);
            const unsigned wb10 = s_w2p[(8 * kb + q) * W2P_STRIDE + 8 + g];
            const unsigned wb11 = s_w2p[(8 * kb + q + 4) * W2P_STRIDE + 8 + g];
            mma16816(o10, o11, o12, o13, ga0, ga1, ga2, ga3, wb10, wb11);
        }
        __syncwarp();   // protect g smem before next iteration overwrites it

        // ---- epilogue: out = mlp + b2 + flat*scales (exact fp32 residual) ----
        #pragma unroll
        for (int nb2 = 0; nb2 < 2; ++nb2) {
            const int ob  = 8 * nb2 + 2 * q;            // o = ob, ob+1
            const int r   = ob >> 2;                    // sub-row within tile
            const int c   = ob & 3;                     // sub-col within tile
            const float2 bb = *reinterpret_cast<const float2*>(s_b2 + ob);
            const float2 ss = *reinterpret_cast<const float2*>(s_sc + ob);
            const size_t rowOff = (size_t)(rowA + r) * 4096;
            const int ca = bcol + (twb + g) * 4 + c;
            const int cb = ca + 32;
            const float2 fa = *reinterpret_cast<const float2*>(A + rowOff + ca);
            const float2 fb = *reinterpret_cast<const float2*>(A + rowOff + cb);
            float p0, p1, p2, p3;
            if (nb2 == 0) { p0 = o00; p1 = o01; p2 = o02; p3 = o03; }
            else          { p0 = o10; p1 = o11; p2 = o12; p3 = o13; }
            float2 ra, rb;
            ra.x = p0 + bb.x + fa.x * ss.x;
            ra.y = p1 + bb.y + fa.y * ss.y;
            rb.x = p2 + bb.x + fb.x * ss.x;
            rb.y = p3 + bb.y + fb.y * ss.y;
            *reinterpret_cast<float2*>(out + rowOff + ca) = ra;
            *reinterpret_cast<float2*>(out + rowOff + cb) = rb;
        }
    }
}

extern "C" void kernel_launch(void* const* d_in, const int* in_sizes, int n_in,
                              void* d_out, int out_size) {
    const float* A      = (const float*)d_in[0];
    const float* w1     = (const float*)d_in[1];
    const float* b1     = (const float*)d_in[2];
    const float* emb_h  = (const float*)d_in[3];
    const float* emb_w  = (const float*)d_in[4];
    const float* w2     = (const float*)d_in[5];
    const float* b2     = (const float*)d_in[6];
    const float* scales = (const float*)d_in[7];
    float* out = (float*)d_out;
    (void)in_sizes; (void)n_in; (void)out_size;

    adapter_mma_kernel<<<4096, 128>>>(A, w1, b1, emb_h, emb_w, w2, b2, scales, out);
}

// round 4
// speedup vs baseline: 4.1440x; 1.6019x over previous
#include <cuda_runtime.h>
#include <cuda_bf16.h>

// ---------- packed helpers ----------
__device__ __forceinline__ unsigned pkbf(float lo, float hi) {
    unsigned d; asm("cvt.rn.bf16x2.f32 %0, %1, %2;" : "=r"(d) : "f"(hi), "f"(lo)); return d;
}
__device__ __forceinline__ unsigned hmin2(unsigned a, unsigned b) {
    unsigned d; asm("min.bf16x2 %0, %1, %2;" : "=r"(d) : "r"(a), "r"(b)); return d;
}
__device__ __forceinline__ unsigned hmax2(unsigned a, unsigned b) {
    unsigned d; asm("max.bf16x2 %0, %1, %2;" : "=r"(d) : "r"(a), "r"(b)); return d;
}
__device__ __forceinline__ unsigned hmul2(unsigned a, unsigned b) {
    unsigned d; asm("mul.rn.bf16x2 %0, %1, %2;" : "=r"(d) : "r"(a), "r"(b)); return d;
}
__device__ __forceinline__ unsigned hadd2(unsigned a, unsigned b) {
    unsigned d; asm("add.rn.bf16x2 %0, %1, %2;" : "=r"(d) : "r"(a), "r"(b)); return d;
}
__device__ __forceinline__ unsigned hex2(unsigned a) {
    unsigned d; asm("ex2.approx.ftz.bf16x2 %0, %1;" : "=r"(d) : "r"(a)); return d;
}
// packed ELU: max(x,0) + exp2(min(x,0)*log2e) - 1   (exact 0 contribution for x>0)
__device__ __forceinline__ unsigned elu2(unsigned x, unsigned l2e, unsigned m1) {
    const unsigned xn = hmin2(x, 0u);
    const unsigned xp = hmax2(x, 0u);
    const unsigned e  = hex2(hmul2(xn, l2e));
    return hadd2(hadd2(xp, e), m1);
}
__device__ __forceinline__ void mma16816(float& d0, float& d1, float& d2, float& d3,
                                         unsigned a0, unsigned a1, unsigned a2, unsigned a3,
                                         unsigned b0, unsigned b1) {
    asm("mma.sync.aligned.m16n8k16.row.col.f32.bf16.bf16.f32 "
        "{%0,%1,%2,%3},{%4,%5,%6,%7},{%8,%9},{%0,%1,%2,%3};"
        : "+f"(d0), "+f"(d1), "+f"(d2), "+f"(d3)
        : "r"(a0), "r"(a1), "r"(a2), "r"(a3), "r"(b0), "r"(b1));
}

// Fixed shapes: A 4096x4096 fp32; 256 weight-blocks of 64x64=4096 4x4-tiles;
// RNG_HID=96, RNG_POS_EMB=8.
// Grid 4096 CTAs x 256 threads (8 warps). CTA = 256 tiles = 16 M-blocks of 16
// tiles; warp w does M-blocks 2w, 2w+1. Layer-1 D fragments map 1:1 onto
// layer-2 A fragments (same thread, same registers) -> elu(hid) never leaves
// registers.
#define W1P_STRIDE 104   // 104 % 32 == 8 -> per-(q,g) banks distinct
#define W2P_STRIDE 24    // 24 % 32 == 24 -> per-(q,g) banks distinct

__global__ __launch_bounds__(256, 2) void adapter_mma_kernel(
    const float* __restrict__ A,        // [4096,4096]
    const float* __restrict__ w1,       // [256,16,96]
    const float* __restrict__ b1,       // [256,96]
    const float* __restrict__ emb_h,    // [256,64,8]
    const float* __restrict__ emb_w,    // [256,64,8]
    const float* __restrict__ w2,       // [256,96,16]
    const float* __restrict__ b2,       // [256,16]
    const float* __restrict__ scales,   // [256,16]
    float* __restrict__ out)            // [4096,4096]
{
    __shared__ __align__(16) unsigned s_w1p[8 * W1P_STRIDE];   // bf16x2 k-pairs of w1
    __shared__ __align__(16) unsigned s_w2p[48 * W2P_STRIDE];  // bf16x2 h-pairs of w2
    __shared__ __align__(16) float s_b1[96];
    __shared__ __align__(16) float s_eh[64 * 8];
    __shared__ __align__(16) float s_ew[64 * 8];
    __shared__ __align__(16) float s_b2[16];
    __shared__ __align__(16) float s_sc[16];

    const int b     = blockIdx.x >> 4;
    const int chunk = blockIdx.x & 15;
    const int tid   = threadIdx.x;       // 0..255
    const int warp  = tid >> 5;          // 0..7
    const int lane  = tid & 31;
    const int g     = lane >> 2;         // 0..7
    const int q     = lane & 3;          // 0..3

    // ---- stage packed weights + biases/embeddings ----
    {
        const float* p1 = w1 + b * 1536;   // [16][96]
        const float* p2 = w2 + b * 1536;   // [96][16]
        #pragma unroll
        for (int i = tid; i < 768; i += 256) {
            const int kp = i / 96, n = i - kp * 96;
            s_w1p[kp * W1P_STRIDE + n] = pkbf(p1[(2 * kp) * 96 + n], p1[(2 * kp + 1) * 96 + n]);
        }
        #pragma unroll
        for (int i = tid; i < 768; i += 256) {
            const int kp = i / 16, n = i & 15;
            s_w2p[kp * W2P_STRIDE + n] = pkbf(p2[(2 * kp) * 16 + n], p2[(2 * kp + 1) * 16 + n]);
        }
        #pragma unroll
        for (int i = 0; i < 2; ++i) {
            s_eh[tid + 256 * i] = emb_h[b * 512 + tid + 256 * i];
            s_ew[tid + 256 * i] = emb_w[b * 512 + tid + 256 * i];
        }
        if (tid < 96) s_b1[tid] = b1[b * 96 + tid];
        if (tid < 16) { s_b2[tid] = b2[b * 16 + tid]; s_sc[tid] = scales[b * 16 + tid]; }
    }
    __syncthreads();

    const int brow = (b >> 4) << 8;
    const int bcol = (b & 15) << 8;
    const unsigned PK_L2E = pkbf(1.44269504f, 1.44269504f);
    const unsigned PK_M1  = pkbf(-1.f, -1.f);

    #pragma unroll
    for (int it = 0; it < 2; ++it) {
        const int mb  = warp * 2 + it;               // M-block 0..15
        const int t0  = chunk * 256 + mb * 16;
        const int th  = t0 >> 6;
        const int twb = t0 & 63;
        const int rowA = brow + th * 4;
        const int colA = bcol + (twb + g) * 4 + 2 * (q & 1);
        const int rsel = q >> 1;

        // ---- layer-1 A fragment straight from GMEM (coalesced float2) ----
        const float2 v0 = *reinterpret_cast<const float2*>(A + (size_t)(rowA + rsel)     * 4096 + colA);
        const float2 v1 = *reinterpret_cast<const float2*>(A + (size_t)(rowA + rsel)     * 4096 + colA + 32);
        const float2 v2 = *reinterpret_cast<const float2*>(A + (size_t)(rowA + 2 + rsel) * 4096 + colA);
        const float2 v3 = *reinterpret_cast<const float2*>(A + (size_t)(rowA + 2 + rsel) * 4096 + colA + 32);
        const unsigned a0 = pkbf(v0.x, v0.y);
        const unsigned a1 = pkbf(v1.x, v1.y);
        const unsigned a2 = pkbf(v2.x, v2.y);
        const unsigned a3 = pkbf(v3.x, v3.y);

        // ---- layer 1: 12 n-blocks; K=16 = one MMA each; result stays in regs ----
        unsigned ga[24];   // ga[2nb] = elu pack rows g, ga[2nb+1] = rows g+8
        #pragma unroll
        for (int nb = 0; nb < 12; ++nb) {
            const unsigned wb0 = s_w1p[q * W1P_STRIDE + 8 * nb + g];
            const unsigned wb1 = s_w1p[(q + 4) * W1P_STRIDE + 8 * nb + g];
            float d0 = 0.f, d1 = 0.f, d2 = 0.f, d3 = 0.f;
            mma16816(d0, d1, d2, d3, a0, a1, a2, a3, wb0, wb1);

            const float2 bb = *reinterpret_cast<const float2*>(s_b1 + 8 * nb + 2 * q);
            d0 += bb.x; d1 += bb.y; d2 += bb.x; d3 += bb.y;
            if (nb == 0) {   // h<8: row positional emb (same th for whole M-block)
                const float2 e = *reinterpret_cast<const float2*>(s_eh + th * 8 + 2 * q);
                d0 += e.x; d1 += e.y; d2 += e.x; d3 += e.y;
            }
            if (nb == 1) {   // 8<=h<16: col positional emb (tw = twb+g / twb+g+8)
                const float2 ea = *reinterpret_cast<const float2*>(s_ew + (twb + g) * 8 + 2 * q);
                const float2 eb = *reinterpret_cast<const float2*>(s_ew + (twb + g + 8) * 8 + 2 * q);
                d0 += ea.x; d1 += ea.y; d2 += eb.x; d3 += eb.y;
            }
            ga[2 * nb]     = elu2(pkbf(d0, d1), PK_L2E, PK_M1);
            ga[2 * nb + 1] = elu2(pkbf(d2, d3), PK_L2E, PK_M1);
        }

        // ---- layer 2: K=96 in 6 k-steps; A frags = ga (register-resident) ----
        float o00 = 0.f, o01 = 0.f, o02 = 0.f, o03 = 0.f;
        float o10 = 0.f, o11 = 0.f, o12 = 0.f, o13 = 0.f;
        #pragma unroll
        for (int kb = 0; kb < 6; ++kb) {
            const unsigned ka0 = ga[4 * kb];      // (g,   16kb+2q..)
            const unsigned ka1 = ga[4 * kb + 1];  // (g+8, 16kb+2q..)
            const unsigned ka2 = ga[4 * kb + 2];  // (g,   16kb+8+2q..)
            const unsigned ka3 = ga[4 * kb + 3];  // (g+8, 16kb+8+2q..)
            const unsigned wb00 = s_w2p[(8 * kb + q) * W2P_STRIDE + g];
            const unsigned wb01 = s_w2p[(8 * kb + q + 4) * W2P_STRIDE + g];
            mma16816(o00, o01, o02, o03, ka0, ka1, ka2, ka3, wb00, wb01);
            const unsigned wb10 = s_w2p[(8 * kb + q) * W2P_STRIDE + 8 + g];
            const unsigned wb11 = s_w2p[(8 * kb + q + 4) * W2P_STRIDE + 8 + g];
            mma16816(o10, o11, o12, o13, ka0, ka1, ka2, ka3, wb10, wb11);
        }

        // ---- epilogue: out = mlp + b2 + flat*scales (exact fp32 residual) ----
        #pragma unroll
        for (int nb2 = 0; nb2 < 2; ++nb2) {
            const int ob = 8 * nb2 + 2 * q;          // out-channel pair ob, ob+1
            const int r  = ob >> 2;
            const int c  = ob & 3;
            const float2 bb = *reinterpret_cast<const float2*>(s_b2 + ob);
            const float2 ss = *reinterpret_cast<const float2*>(s_sc + ob);
            const size_t rowOff = (size_t)(rowA + r) * 4096;
            const int ca = bcol + (twb + g) * 4 + c;
            const int cb = ca + 32;
            const float2 fa = *reinterpret_cast<const float2*>(A + rowOff + ca);
            const float2 fb = *reinterpret_cast<const float2*>(A + rowOff + cb);
            float p0, p1, p2, p3;
            if (nb2 == 0) { p0 = o00; p1 = o01; p2 = o02; p3 = o03; }
            else          { p0 = o10; p1 = o11; p2 = o12; p3 = o13; }
            float2 ra, rb;
            ra.x = p0 + bb.x + fa.x * ss.x;
            ra.y = p1 + bb.y + fa.y * ss.y;
            rb.x = p2 + bb.x + fb.x * ss.x;
            rb.y = p3 + bb.y + fb.y * ss.y;
            *reinterpret_cast<float2*>(out + rowOff + ca) = ra;
            *reinterpret_cast<float2*>(out + rowOff + cb) = rb;
        }
    }
}

extern "C" void kernel_launch(void* const* d_in, const int* in_sizes, int n_in,
                              void* d_out, int out_size) {
    const float* A      = (const float*)d_in[0];
    const float* w1     = (const float*)d_in[1];
    const float* b1     = (const float*)d_in[2];
    const float* emb_h  = (const float*)d_in[3];
    const float* emb_w  = (const float*)d_in[4];
    const float* w2     = (const float*)d_in[5];
    const float* b2     = (const float*)d_in[6];
    const float* scales = (const float*)d_in[7];
    float* out = (float*)d_out;
    (void)in_sizes; (void)n_in; (void)out_size;

    adapter_mma_kernel<<<4096, 256>>>(A, w1, b1, emb_h, emb_w, w2, b2, scales, out);
}

// round 5
// speedup vs baseline: 4.6504x; 1.1222x over previous
#include <cuda_runtime.h>
#include <cuda_bf16.h>

// ---------- packed helpers ----------
__device__ __forceinline__ unsigned pkbf(float lo, float hi) {
    unsigned d; asm("cvt.rn.bf16x2.f32 %0, %1, %2;" : "=r"(d) : "f"(hi), "f"(lo)); return d;
}
__device__ __forceinline__ unsigned hmin2(unsigned a, unsigned b) {
    unsigned d; asm("min.bf16x2 %0, %1, %2;" : "=r"(d) : "r"(a), "r"(b)); return d;
}
__device__ __forceinline__ unsigned hmax2(unsigned a, unsigned b) {
    unsigned d; asm("max.bf16x2 %0, %1, %2;" : "=r"(d) : "r"(a), "r"(b)); return d;
}
__device__ __forceinline__ unsigned hmul2(unsigned a, unsigned b) {
    unsigned d; asm("mul.rn.bf16x2 %0, %1, %2;" : "=r"(d) : "r"(a), "r"(b)); return d;
}
__device__ __forceinline__ unsigned hadd2(unsigned a, unsigned b) {
    unsigned d; asm("add.rn.bf16x2 %0, %1, %2;" : "=r"(d) : "r"(a), "r"(b)); return d;
}
__device__ __forceinline__ unsigned hex2(unsigned a) {
    unsigned d; asm("ex2.approx.ftz.bf16x2 %0, %1;" : "=r"(d) : "r"(a)); return d;
}
// shifted packed ELU: elu(x)+1 = max(x,0) + exp2(min(x,0)*log2e)
__device__ __forceinline__ unsigned elu2s(unsigned x, unsigned l2e) {
    return hadd2(hmax2(x, 0u), hex2(hmul2(hmin2(x, 0u), l2e)));
}
__device__ __forceinline__ void mma16816(float& d0, float& d1, float& d2, float& d3,
                                         unsigned a0, unsigned a1, unsigned a2, unsigned a3,
                                         unsigned b0, unsigned b1) {
    asm("mma.sync.aligned.m16n8k16.row.col.f32.bf16.bf16.f32 "
        "{%0,%1,%2,%3},{%4,%5,%6,%7},{%8,%9},{%0,%1,%2,%3};"
        : "+f"(d0), "+f"(d1), "+f"(d2), "+f"(d3)
        : "r"(a0), "r"(a1), "r"(a2), "r"(a3), "r"(b0), "r"(b1));
}

// Fixed shapes: A 4096x4096 fp32; 256 weight-blocks of 64x64=4096 4x4-tiles;
// RNG_HID=96, RNG_POS_EMB=8.
// Grid 4096 CTAs x 256 threads (8 warps). Warp w owns M-blocks 2w, 2w+1 and
// processes them together, kb-by-kb over the hidden dim (fused L1->ELU->L2),
// so each weight-fragment LDS serves both M-blocks and activations stay in 8
// transient registers.
#define S1 100   // uint2 stride for w1 pairs: bank = (8q+2g+16nb)%32, conflict-free
#define S2 20    // uint2 stride for w2 pairs: bank = (8q+2n)%32, conflict-free

__global__ __launch_bounds__(256, 3) void adapter_mma_kernel(
    const float* __restrict__ A,        // [4096,4096]
    const float* __restrict__ w1,       // [256,16,96]
    const float* __restrict__ b1,       // [256,96]
    const float* __restrict__ emb_h,    // [256,64,8]
    const float* __restrict__ emb_w,    // [256,64,8]
    const float* __restrict__ w2,       // [256,96,16]
    const float* __restrict__ b2,       // [256,16]
    const float* __restrict__ scales,   // [256,16]
    float* __restrict__ out)            // [4096,4096]
{
    __shared__ __align__(16) uint2 s_w1b[4 * S1];    // [q][h]: {k=2q pair, k=2q+8 pair}
    __shared__ __align__(16) uint2 s_w2b[24 * S2];   // [4kb+q][n]: {h=16kb+2q pair, +8 pair}
    __shared__ __align__(16) float s_b1[96];
    __shared__ __align__(16) float s_eh[64 * 8];
    __shared__ __align__(16) float s_ew[64 * 8];
    __shared__ __align__(16) float s_psum[8 * 16];   // w2 colsum partials
    __shared__ __align__(16) float s_b2e[16];        // b2 - colsum(w2)
    __shared__ __align__(16) float s_sc[16];

    const int b     = blockIdx.x >> 4;
    const int chunk = blockIdx.x & 15;
    const int tid   = threadIdx.x;
    const int warp  = tid >> 5;
    const int lane  = tid & 31;
    const int g     = lane >> 2;     // 0..7
    const int q     = lane & 3;      // 0..3

    // ---- stage packed weight-pair fragments + biases/embeddings ----
    {
        const float* p1 = w1 + b * 1536;   // [16][96]
        const float* p2 = w2 + b * 1536;   // [96][16]
        #pragma unroll
        for (int i = tid; i < 384; i += 256) {
            const int qq = i / 96, h = i - qq * 96;
            s_w1b[qq * S1 + h] = make_uint2(
                pkbf(p1[(2 * qq) * 96 + h],     p1[(2 * qq + 1) * 96 + h]),
                pkbf(p1[(2 * qq + 8) * 96 + h], p1[(2 * qq + 9) * 96 + h]));
        }
        #pragma unroll
        for (int i = tid; i < 384; i += 256) {
            const int kq = i >> 4, n = i & 15;     // kq = 4*kb+q
            const int h0 = (kq >> 2) * 16 + 2 * (kq & 3);
            s_w2b[kq * S2 + n] = make_uint2(
                pkbf(p2[h0 * 16 + n],       p2[(h0 + 1) * 16 + n]),
                pkbf(p2[(h0 + 8) * 16 + n], p2[(h0 + 9) * 16 + n]));
        }
        #pragma unroll
        for (int i = 0; i < 2; ++i) {
            s_eh[tid + 256 * i] = emb_h[b * 512 + tid + 256 * i];
            s_ew[tid + 256 * i] = emb_w[b * 512 + tid + 256 * i];
        }
        if (tid < 96) s_b1[tid] = b1[b * 96 + tid];
        if (tid < 128) {   // w2 column-sum partials: thread = part p (0..7) x col o
            const int o = tid & 15, p = tid >> 4;
            float s = 0.f;
            #pragma unroll
            for (int h = 0; h < 12; ++h) s += p2[(12 * p + h) * 16 + o];
            s_psum[p * 16 + o] = s;
        }
    }
    __syncthreads();
    if (tid < 16) {
        float s = b2[b * 16 + tid];
        #pragma unroll
        for (int p = 0; p < 8; ++p) s -= s_psum[p * 16 + tid];
        s_b2e[tid] = s;
        s_sc[tid]  = scales[b * 16 + tid];
    }
    __syncthreads();

    const int brow = (b >> 4) << 8;
    const int bcol = (b & 15) << 8;
    const unsigned PK_L2E = pkbf(1.44269504f, 1.44269504f);

    // ---- per-it geometry + layer-1 A fragments straight from GMEM ----
    unsigned Af[2][4];
    int thv[2], twbv[2], rowAv[2];
    const int rsel = q >> 1;
    #pragma unroll
    for (int it = 0; it < 2; ++it) {
        const int mb  = warp * 2 + it;
        const int t0  = chunk * 256 + mb * 16;
        thv[it]  = t0 >> 6;
        twbv[it] = t0 & 63;
        rowAv[it] = brow + thv[it] * 4;
        const int colA = bcol + (twbv[it] + g) * 4 + 2 * (q & 1);
        const float2 v0 = *reinterpret_cast<const float2*>(A + (size_t)(rowAv[it] + rsel)     * 4096 + colA);
        const float2 v1 = *reinterpret_cast<const float2*>(A + (size_t)(rowAv[it] + rsel)     * 4096 + colA + 32);
        const float2 v2 = *reinterpret_cast<const float2*>(A + (size_t)(rowAv[it] + 2 + rsel) * 4096 + colA);
        const float2 v3 = *reinterpret_cast<const float2*>(A + (size_t)(rowAv[it] + 2 + rsel) * 4096 + colA + 32);
        Af[it][0] = pkbf(v0.x, v0.y);
        Af[it][1] = pkbf(v1.x, v1.y);
        Af[it][2] = pkbf(v2.x, v2.y);
        Af[it][3] = pkbf(v3.x, v3.y);
    }

    float o[2][8];
    #pragma unroll
    for (int it = 0; it < 2; ++it)
        #pragma unroll
        for (int j = 0; j < 8; ++j) o[it][j] = 0.f;

    // ---- fused mainloop over hidden dim: 6 kb-steps ----
    #pragma unroll
    for (int kb = 0; kb < 6; ++kb) {
        unsigned ka[2][4];
        #pragma unroll
        for (int sub = 0; sub < 2; ++sub) {
            const int nb = 2 * kb + sub;
            const uint2 wp  = s_w1b[q * S1 + 8 * nb + g];               // one LDS.64, both its
            const float2 bb = *reinterpret_cast<const float2*>(s_b1 + 8 * nb + 2 * q);
            #pragma unroll
            for (int it = 0; it < 2; ++it) {
                float d0 = bb.x, d1 = bb.y, d2 = bb.x, d3 = bb.y;       // bias as C-init
                if (nb == 0) {   // h<8: row positional emb (constant over M-block)
                    const float2 e = *reinterpret_cast<const float2*>(s_eh + thv[it] * 8 + 2 * q);
                    d0 += e.x; d1 += e.y; d2 += e.x; d3 += e.y;
                }
                if (nb == 1) {   // 8<=h<16: col positional emb
                    const float2 ea = *reinterpret_cast<const float2*>(s_ew + (twbv[it] + g) * 8 + 2 * q);
                    const float2 eb = *reinterpret_cast<const float2*>(s_ew + (twbv[it] + g + 8) * 8 + 2 * q);
                    d0 += ea.x; d1 += ea.y; d2 += eb.x; d3 += eb.y;
                }
                mma16816(d0, d1, d2, d3, Af[it][0], Af[it][1], Af[it][2], Af[it][3], wp.x, wp.y);
                ka[it][2 * sub]     = elu2s(pkbf(d0, d1), PK_L2E);      // rows g
                ka[it][2 * sub + 1] = elu2s(pkbf(d2, d3), PK_L2E);      // rows g+8
            }
        }
        const uint2 wa = s_w2b[(4 * kb + q) * S2 + g];       // n = g
        const uint2 wbb = s_w2b[(4 * kb + q) * S2 + 8 + g];  // n = g+8
        #pragma unroll
        for (int it = 0; it < 2; ++it) {
            mma16816(o[it][0], o[it][1], o[it][2], o[it][3],
                     ka[it][0], ka[it][1], ka[it][2], ka[it][3], wa.x, wa.y);
            mma16816(o[it][4], o[it][5], o[it][6], o[it][7],
                     ka[it][0], ka[it][1], ka[it][2], ka[it][3], wbb.x, wbb.y);
        }
    }

    // ---- epilogue: out = mlp + b2_eff + flat*scales (exact fp32 residual) ----
    #pragma unroll
    for (int it = 0; it < 2; ++it) {
        #pragma unroll
        for (int nb2 = 0; nb2 < 2; ++nb2) {
            const int ob = 8 * nb2 + 2 * q;
            const int r  = ob >> 2;
            const int c  = ob & 3;
            const float2 bb = *reinterpret_cast<const float2*>(s_b2e + ob);
            const float2 ss = *reinterpret_cast<const float2*>(s_sc + ob);
            const size_t rowOff = (size_t)(rowAv[it] + r) * 4096;
            const int ca = bcol + (twbv[it] + g) * 4 + c;
            const int cb = ca + 32;
            const float2 fa = *reinterpret_cast<const float2*>(A + rowOff + ca);
            const float2 fb = *reinterpret_cast<const float2*>(A + rowOff + cb);
            const float p0 = o[it][4 * nb2 + 0];
            const float p1 = o[it][4 * nb2 + 1];
            const float p2v = o[it][4 * nb2 + 2];
            const float p3 = o[it][4 * nb2 + 3];
            float2 ra, rb;
            ra.x = p0  + bb.x + fa.x * ss.x;
            ra.y = p1  + bb.y + fa.y * ss.y;
            rb.x = p2v + bb.x + fb.x * ss.x;
            rb.y = p3  + bb.y + fb.y * ss.y;
            *reinterpret_cast<float2*>(out + rowOff + ca) = ra;
            *reinterpret_cast<float2*>(out + rowOff + cb) = rb;
        }
    }
}

extern "C" void kernel_launch(void* const* d_in, const int* in_sizes, int n_in,
                              void* d_out, int out_size) {
    const float* A      = (const float*)d_in[0];
    const float* w1     = (const float*)d_in[1];
    const float* b1     = (const float*)d_in[2];
    const float* emb_h  = (const float*)d_in[3];
    const float* emb_w  = (const float*)d_in[4];
    const float* w2     = (const float*)d_in[5];
    const float* b2     = (const float*)d_in[6];
    const float* scales = (const float*)d_in[7];
    float* out = (float*)d_out;
    (void)in_sizes; (void)n_in; (void)out_size;

    adapter_mma_kernel<<<4096, 256>>>(A, w1, b1, emb_h, emb_w, w2, b2, scales, out);
}